// round 14
// baseline (speedup 1.0000x reference)
#include <cuda_runtime.h>
#include <math.h>

#define MAXN 100000
#define MAXE 1600000

// ---------------- static device scratch (no allocations allowed) ----------------
__device__ int    d_deg[MAXN];
__device__ int    d_off[MAXN + 1];
__device__ int    d_pos[MAXN];
__device__ int    d_srcs[MAXE];
__device__ int    d_bsums[128];
__device__ float  d_Z1[(size_t)MAXN * 128];   // x@W1_l^T  (later reused as Z2|P2)
__device__ float  d_P1[(size_t)MAXN * 128];   // x@W1_r^T + b1, becomes h in-place
__device__ double d_bnsum[128];
__device__ double d_bnsq[128];
__device__ float  d_scale[128];
__device__ float  d_shift[128];

// ---------------- init: zero counters ----------------
__global__ void k_init(int n) {
    int i = blockIdx.x * 512 + threadIdx.x;
    if (i < n) { d_deg[i] = 0; d_pos[i] = 0; }
    if (i < 128) { d_bnsum[i] = 0.0; d_bnsq[i] = 0.0; }
}

// ---------------- CSR build (edge_index is int32: JAX default x64=off) ----------
__global__ void k_hist(const int* __restrict__ ei, int E, int n) {
    int e = blockIdx.x * 256 + threadIdx.x;
    if (e >= E) return;
    int d = ei[E + e];
    if ((unsigned)d < (unsigned)n) atomicAdd(&d_deg[d], 1);
}

__global__ void k_scan1(int n) {
    int i = blockIdx.x * 1024 + threadIdx.x;
    int v = (i < n) ? d_deg[i] : 0;
    int lane = threadIdx.x & 31, wid = threadIdx.x >> 5;
    int x = v;
#pragma unroll
    for (int d = 1; d < 32; d <<= 1) {
        int y = __shfl_up_sync(0xffffffffu, x, d);
        if (lane >= d) x += y;
    }
    __shared__ int ws[32];
    if (lane == 31) ws[wid] = x;
    __syncthreads();
    if (wid == 0) {
        int s = ws[lane];
#pragma unroll
        for (int d = 1; d < 32; d <<= 1) {
            int y = __shfl_up_sync(0xffffffffu, s, d);
            if (lane >= d) s += y;
        }
        ws[lane] = s;
    }
    __syncthreads();
    int pref = (wid > 0) ? ws[wid - 1] : 0;
    int incl = pref + x;
    if (i < n) d_off[i] = incl - v;
    if (threadIdx.x == 1023) d_bsums[blockIdx.x] = incl;
}

__global__ void k_scan2(int nb) {   // nb <= 128
    int t = threadIdx.x;
    int v = (t < nb) ? d_bsums[t] : 0;
    int lane = t & 31, wid = t >> 5;
    int x = v;
#pragma unroll
    for (int d = 1; d < 32; d <<= 1) {
        int y = __shfl_up_sync(0xffffffffu, x, d);
        if (lane >= d) x += y;
    }
    __shared__ int ws[4];
    if (lane == 31) ws[wid] = x;
    __syncthreads();
    int pref = 0;
    for (int w = 0; w < wid; w++) pref += ws[w];
    int incl = pref + x;
    if (t < nb) d_bsums[t] = incl - v;
}

__global__ void k_scan3(int n, int E) {
    int i = blockIdx.x * 1024 + threadIdx.x;
    if (i < n) d_off[i] += d_bsums[blockIdx.x];
    if (blockIdx.x == 0 && threadIdx.x == 0) d_off[n] = E;
}

__global__ void k_scatter(const int* __restrict__ ei, int E, int n) {
    int e = blockIdx.x * 256 + threadIdx.x;
    if (e >= E) return;
    int s = ei[e];
    int d = ei[E + e];
    if ((unsigned)d >= (unsigned)n || (unsigned)s >= (unsigned)n) return;
    int idx = d_off[d] + atomicAdd(&d_pos[d], 1);
    d_srcs[idx] = s;
}

// ---------------- GEMM1: Z1 = x@W1_l^T ; P1 = x@W1_r^T + b1 ----------------
// B = concat(W1_l, W1_r) as [256 rows j][128 cols k], fully smem-resident.
__global__ __launch_bounds__(512, 1)
void k_gemm1(const float* __restrict__ x, const float* __restrict__ Wl,
             const float* __restrict__ Wr, const float* __restrict__ bias, int n) {
    extern __shared__ float sm[];
    float* As = sm;               // [128][129]
    float* Bs = sm + 128 * 129;   // [256][129]
    const int tid = threadIdx.x;
    const int m0 = blockIdx.x * 128;

    for (int idx = tid; idx < 128 * 128; idx += 512) {
        int m = idx >> 7, k = idx & 127;
        int gm = m0 + m;
        As[m * 129 + k] = (gm < n) ? x[(size_t)gm * 128 + k] : 0.f;
        Bs[m * 129 + k] = Wl[idx];            // m plays role of j here
        Bs[(128 + m) * 129 + k] = Wr[idx];
    }
    __syncthreads();

    const int tm = (tid & 15) * 8;   // 16 groups * 8 = 128 rows
    const int tj = (tid >> 4) * 8;   // 32 groups * 8 = 256 cols
    float acc[8][8];
#pragma unroll
    for (int i = 0; i < 8; i++)
#pragma unroll
        for (int j = 0; j < 8; j++) acc[i][j] = 0.f;

#pragma unroll 4
    for (int k = 0; k < 128; k++) {
        float a[8], b[8];
#pragma unroll
        for (int i = 0; i < 8; i++) a[i] = As[(tm + i) * 129 + k];
#pragma unroll
        for (int j = 0; j < 8; j++) b[j] = Bs[(tj + j) * 129 + k];
#pragma unroll
        for (int i = 0; i < 8; i++)
#pragma unroll
            for (int j = 0; j < 8; j++) acc[i][j] = fmaf(a[i], b[j], acc[i][j]);
    }

    const bool isP = (tj >= 128);
    float bj[8];
#pragma unroll
    for (int j = 0; j < 8; j++) bj[j] = isP ? bias[tj - 128 + j] : 0.f;

#pragma unroll
    for (int i = 0; i < 8; i++) {
        int gm = m0 + tm + i;
        if (gm >= n) continue;
        float4 v0 = make_float4(acc[i][0] + bj[0], acc[i][1] + bj[1],
                                acc[i][2] + bj[2], acc[i][3] + bj[3]);
        float4 v1 = make_float4(acc[i][4] + bj[4], acc[i][5] + bj[5],
                                acc[i][6] + bj[6], acc[i][7] + bj[7]);
        float* dst = isP ? (d_P1 + (size_t)gm * 128 + (tj - 128))
                         : (d_Z1 + (size_t)gm * 128 + tj);
        *(float4*)dst = v0;
        *(float4*)(dst + 4) = v1;
    }
}

// ---------------- agg1: h = P1 + mean-gather(Z1); BN partial sums ----------------
__global__ __launch_bounds__(256)
void k_agg1(int n) {
    __shared__ float ssum[128], ssq[128];
    int tid = threadIdx.x;
    if (tid < 128) { ssum[tid] = 0.f; ssq[tid] = 0.f; }
    __syncthreads();
    int lane = tid & 31, warp = tid >> 5;
    int node = blockIdx.x * 8 + warp;
    if (node < n) {
        int a = d_off[node], b = d_off[node + 1];
        float4 acc = make_float4(0.f, 0.f, 0.f, 0.f);
        int e = a;
        for (; e + 4 <= b; e += 4) {
            int s0 = d_srcs[e], s1 = d_srcs[e + 1], s2 = d_srcs[e + 2], s3 = d_srcs[e + 3];
            float4 v0 = *(const float4*)&d_Z1[(size_t)s0 * 128 + lane * 4];
            float4 v1 = *(const float4*)&d_Z1[(size_t)s1 * 128 + lane * 4];
            float4 v2 = *(const float4*)&d_Z1[(size_t)s2 * 128 + lane * 4];
            float4 v3 = *(const float4*)&d_Z1[(size_t)s3 * 128 + lane * 4];
            acc.x += (v0.x + v1.x) + (v2.x + v3.x);
            acc.y += (v0.y + v1.y) + (v2.y + v3.y);
            acc.z += (v0.z + v1.z) + (v2.z + v3.z);
            acc.w += (v0.w + v1.w) + (v2.w + v3.w);
        }
        for (; e < b; e++) {
            int s = d_srcs[e];
            float4 v = *(const float4*)&d_Z1[(size_t)s * 128 + lane * 4];
            acc.x += v.x; acc.y += v.y; acc.z += v.z; acc.w += v.w;
        }
        int cnt = b - a;
        float inv = 1.0f / (float)(cnt > 0 ? cnt : 1);
        float4 p = *(const float4*)&d_P1[(size_t)node * 128 + lane * 4];
        float4 h;
        h.x = fmaf(acc.x, inv, p.x);
        h.y = fmaf(acc.y, inv, p.y);
        h.z = fmaf(acc.z, inv, p.z);
        h.w = fmaf(acc.w, inv, p.w);
        *(float4*)&d_P1[(size_t)node * 128 + lane * 4] = h;
        int c = lane * 4;
        atomicAdd(&ssum[c + 0], h.x); atomicAdd(&ssq[c + 0], h.x * h.x);
        atomicAdd(&ssum[c + 1], h.y); atomicAdd(&ssq[c + 1], h.y * h.y);
        atomicAdd(&ssum[c + 2], h.z); atomicAdd(&ssq[c + 2], h.z * h.z);
        atomicAdd(&ssum[c + 3], h.w); atomicAdd(&ssq[c + 3], h.w * h.w);
    }
    __syncthreads();
    if (tid < 128) {
        atomicAdd(&d_bnsum[tid], (double)ssum[tid]);
        atomicAdd(&d_bnsq[tid], (double)ssq[tid]);
    }
}

// ---------------- BN finalize ----------------
__global__ void k_bnfin(const float* __restrict__ gamma, const float* __restrict__ beta, int n) {
    int c = threadIdx.x;  // 128 threads
    double mean = d_bnsum[c] / (double)n;
    double var = d_bnsq[c] / (double)n - mean * mean;
    float rs = rsqrtf((float)var + 1e-5f);
    float sc = gamma[c] * rs;
    d_scale[c] = sc;
    d_shift[c] = beta[c] - (float)mean * sc;
}

// ---------------- GEMM2: hn = relu(BN(h)); Z2 = hn@W2_l^T ; P2 = hn@W2_r^T ----------------
__global__ __launch_bounds__(512, 1)
void k_gemm2(const float* __restrict__ Wl, const float* __restrict__ Wr, int n) {
    extern __shared__ float sm[];
    float* As  = sm;                  // [128][129]
    float* Bs  = sm + 128 * 129;      // [128][129]
    float* ssc = Bs + 128 * 129;      // [128]
    float* ssh = ssc + 128;           // [128]
    const int tid = threadIdx.x;
    if (tid < 128) { ssc[tid] = d_scale[tid]; ssh[tid] = d_shift[tid]; }
    __syncthreads();
    const int m0 = blockIdx.x * 128;

    for (int idx = tid; idx < 128 * 128; idx += 512) {
        int m = idx >> 7, k = idx & 127;
        int gm = m0 + m;
        float v = 0.f;
        if (gm < n) {
            v = d_P1[(size_t)gm * 128 + k];
            v = fmaxf(fmaf(v, ssc[k], ssh[k]), 0.f);
        }
        As[m * 129 + k] = v;
    }
    for (int idx = tid; idx < 64 * 128; idx += 512) {
        int j = idx >> 7, k = idx & 127;
        Bs[j * 129 + k] = Wl[idx];
        Bs[(64 + j) * 129 + k] = Wr[idx];
    }
    __syncthreads();

    const int tm = (tid & 15) * 8;   // 128 rows
    const int tj = (tid >> 4) * 4;   // 32 groups * 4 = 128 cols
    float acc[8][4];
#pragma unroll
    for (int i = 0; i < 8; i++)
#pragma unroll
        for (int j = 0; j < 4; j++) acc[i][j] = 0.f;

#pragma unroll 4
    for (int k = 0; k < 128; k++) {
        float a[8], b[4];
#pragma unroll
        for (int i = 0; i < 8; i++) a[i] = As[(tm + i) * 129 + k];
#pragma unroll
        for (int j = 0; j < 4; j++) b[j] = Bs[(tj + j) * 129 + k];
#pragma unroll
        for (int i = 0; i < 8; i++)
#pragma unroll
            for (int j = 0; j < 4; j++) acc[i][j] = fmaf(a[i], b[j], acc[i][j]);
    }

    float* Z2 = d_Z1;
    float* P2 = d_Z1 + (size_t)n * 64;
    const bool isP = (tj >= 64);
#pragma unroll
    for (int i = 0; i < 8; i++) {
        int gm = m0 + tm + i;
        if (gm >= n) continue;
        float4 v = make_float4(acc[i][0], acc[i][1], acc[i][2], acc[i][3]);
        float* dst = isP ? (P2 + (size_t)gm * 64 + (tj - 64))
                         : (Z2 + (size_t)gm * 64 + tj);
        *(float4*)dst = v;
    }
}

// ---------------- agg2 + bias + log_softmax ----------------
__global__ __launch_bounds__(256)
void k_agg2(const float* __restrict__ b2, float* __restrict__ out, int n) {
    int tid = threadIdx.x, lane = tid & 31, warp = tid >> 5;
    int node = blockIdx.x * 8 + warp;
    if (node >= n) return;
    const float* Z2 = d_Z1;
    const float* P2 = d_Z1 + (size_t)n * 64;
    int a = d_off[node], b = d_off[node + 1];
    float2 acc = make_float2(0.f, 0.f);
    int e = a;
    for (; e + 4 <= b; e += 4) {
        int s0 = d_srcs[e], s1 = d_srcs[e + 1], s2 = d_srcs[e + 2], s3 = d_srcs[e + 3];
        float2 v0 = *(const float2*)&Z2[(size_t)s0 * 64 + lane * 2];
        float2 v1 = *(const float2*)&Z2[(size_t)s1 * 64 + lane * 2];
        float2 v2 = *(const float2*)&Z2[(size_t)s2 * 64 + lane * 2];
        float2 v3 = *(const float2*)&Z2[(size_t)s3 * 64 + lane * 2];
        acc.x += (v0.x + v1.x) + (v2.x + v3.x);
        acc.y += (v0.y + v1.y) + (v2.y + v3.y);
    }
    for (; e < b; e++) {
        int s = d_srcs[e];
        float2 v = *(const float2*)&Z2[(size_t)s * 64 + lane * 2];
        acc.x += v.x; acc.y += v.y;
    }
    int cnt = b - a;
    float inv = 1.0f / (float)(cnt > 0 ? cnt : 1);
    float2 p = *(const float2*)&P2[(size_t)node * 64 + lane * 2];
    float v0 = fmaf(acc.x, inv, p.x) + b2[lane * 2];
    float v1 = fmaf(acc.y, inv, p.y) + b2[lane * 2 + 1];

    float m = fmaxf(v0, v1);
#pragma unroll
    for (int d = 16; d > 0; d >>= 1) m = fmaxf(m, __shfl_xor_sync(0xffffffffu, m, d));
    float s = expf(v0 - m) + expf(v1 - m);
#pragma unroll
    for (int d = 16; d > 0; d >>= 1) s += __shfl_xor_sync(0xffffffffu, s, d);
    float ls = logf(s);
    float2 o = make_float2(v0 - m - ls, v1 - m - ls);
    *(float2*)&out[(size_t)node * 64 + lane * 2] = o;
}

// ---------------- launch ----------------
extern "C" void kernel_launch(void* const* d_in, const int* in_sizes, int n_in,
                              void* d_out, int out_size) {
    const float* x     = (const float*)d_in[0];
    const int*   ei    = (const int*)d_in[1];     // int32: JAX x64 disabled
    const float* W1l   = (const float*)d_in[2];
    const float* b1l   = (const float*)d_in[3];
    const float* W1r   = (const float*)d_in[4];
    const float* gamma = (const float*)d_in[5];
    const float* beta  = (const float*)d_in[6];
    const float* W2l   = (const float*)d_in[7];
    const float* b2l   = (const float*)d_in[8];
    const float* W2r   = (const float*)d_in[9];
    float* out = (float*)d_out;

    int N_ = in_sizes[0] / 128;
    int E_ = in_sizes[1] / 2;

    const int SMEM1 = (128 * 129 + 256 * 129) * 4;          // 198144
    const int SMEM2 = (128 * 129 + 128 * 129 + 256) * 4;    // 133120
    cudaFuncSetAttribute(k_gemm1, cudaFuncAttributeMaxDynamicSharedMemorySize, SMEM1);
    cudaFuncSetAttribute(k_gemm2, cudaFuncAttributeMaxDynamicSharedMemorySize, SMEM2);

    k_init<<<(N_ + 511) / 512, 512>>>(N_);
    k_hist<<<(E_ + 255) / 256, 256>>>(ei, E_, N_);
    int nb = (N_ + 1023) / 1024;
    k_scan1<<<nb, 1024>>>(N_);
    k_scan2<<<1, 128>>>(nb);
    k_scan3<<<nb, 1024>>>(N_, E_);
    k_scatter<<<(E_ + 255) / 256, 256>>>(ei, E_, N_);

    k_gemm1<<<(N_ + 127) / 128, 512, SMEM1>>>(x, W1l, W1r, b1l, N_);
    k_agg1<<<(N_ + 7) / 8, 256>>>(N_);
    k_bnfin<<<1, 128>>>(gamma, beta, N_);
    k_gemm2<<<(N_ + 127) / 128, 512, SMEM2>>>(W2l, W2r, N_);
    k_agg2<<<(N_ + 7) / 8, 256>>>(b2l, out, N_);
}

// round 15
// speedup vs baseline: 1.0002x; 1.0002x over previous
#include <cuda_runtime.h>
#include <math.h>

#define MAXN 100000
#define MAXE 1600000

// ---------------- static device scratch (no allocations allowed) ----------------
__device__ int    d_deg[MAXN];
__device__ int    d_off[MAXN + 1];
__device__ int    d_pos[MAXN];
__device__ int    d_srcs[MAXE];
__device__ int    d_bsums[128];
__device__ float  d_Z1[(size_t)MAXN * 128];   // x@W1_l^T  (later reused as Z2|P2)
__device__ float  d_P1[(size_t)MAXN * 128];   // x@W1_r^T + b1, becomes h in-place
__device__ double d_bnsum[128];
__device__ double d_bnsq[128];
__device__ float  d_scale[128];
__device__ float  d_shift[128];

// ---------------- init: zero counters ----------------
__global__ void k_init(int n) {
    int i = blockIdx.x * 512 + threadIdx.x;
    if (i < n) { d_deg[i] = 0; d_pos[i] = 0; }
    if (i < 128) { d_bnsum[i] = 0.0; d_bnsq[i] = 0.0; }
}

// ---------------- CSR build (edge_index is int32: JAX default x64=off) ----------
__global__ void k_hist(const int* __restrict__ ei, int E, int n) {
    int e = blockIdx.x * 256 + threadIdx.x;
    if (e >= E) return;
    int d = ei[E + e];
    if ((unsigned)d < (unsigned)n) atomicAdd(&d_deg[d], 1);
}

__global__ void k_scan1(int n) {
    int i = blockIdx.x * 1024 + threadIdx.x;
    int v = (i < n) ? d_deg[i] : 0;
    int lane = threadIdx.x & 31, wid = threadIdx.x >> 5;
    int x = v;
#pragma unroll
    for (int d = 1; d < 32; d <<= 1) {
        int y = __shfl_up_sync(0xffffffffu, x, d);
        if (lane >= d) x += y;
    }
    __shared__ int ws[32];
    if (lane == 31) ws[wid] = x;
    __syncthreads();
    if (wid == 0) {
        int s = ws[lane];
#pragma unroll
        for (int d = 1; d < 32; d <<= 1) {
            int y = __shfl_up_sync(0xffffffffu, s, d);
            if (lane >= d) s += y;
        }
        ws[lane] = s;
    }
    __syncthreads();
    int pref = (wid > 0) ? ws[wid - 1] : 0;
    int incl = pref + x;
    if (i < n) d_off[i] = incl - v;
    if (threadIdx.x == 1023) d_bsums[blockIdx.x] = incl;
}

__global__ void k_scan2(int nb) {   // nb <= 128
    int t = threadIdx.x;
    int v = (t < nb) ? d_bsums[t] : 0;
    int lane = t & 31, wid = t >> 5;
    int x = v;
#pragma unroll
    for (int d = 1; d < 32; d <<= 1) {
        int y = __shfl_up_sync(0xffffffffu, x, d);
        if (lane >= d) x += y;
    }
    __shared__ int ws[4];
    if (lane == 31) ws[wid] = x;
    __syncthreads();
    int pref = 0;
    for (int w = 0; w < wid; w++) pref += ws[w];
    int incl = pref + x;
    if (t < nb) d_bsums[t] = incl - v;
}

__global__ void k_scan3(int n, int E) {
    int i = blockIdx.x * 1024 + threadIdx.x;
    if (i < n) d_off[i] += d_bsums[blockIdx.x];
    if (blockIdx.x == 0 && threadIdx.x == 0) d_off[n] = E;
}

__global__ void k_scatter(const int* __restrict__ ei, int E, int n) {
    int e = blockIdx.x * 256 + threadIdx.x;
    if (e >= E) return;
    int s = ei[e];
    int d = ei[E + e];
    if ((unsigned)d >= (unsigned)n || (unsigned)s >= (unsigned)n) return;
    int idx = d_off[d] + atomicAdd(&d_pos[d], 1);
    d_srcs[idx] = s;
}

// ---------------- GEMM1: Z1 = x@W1_l^T ; P1 = x@W1_r^T + b1 ----------------
// B = concat(W1_l, W1_r) as [256 rows j][128 cols k], fully smem-resident.
__global__ __launch_bounds__(512, 1)
void k_gemm1(const float* __restrict__ x, const float* __restrict__ Wl,
             const float* __restrict__ Wr, const float* __restrict__ bias, int n) {
    extern __shared__ float sm[];
    float* As = sm;               // [128][129]
    float* Bs = sm + 128 * 129;   // [256][129]
    const int tid = threadIdx.x;
    const int m0 = blockIdx.x * 128;

    for (int idx = tid; idx < 128 * 128; idx += 512) {
        int m = idx >> 7, k = idx & 127;
        int gm = m0 + m;
        As[m * 129 + k] = (gm < n) ? x[(size_t)gm * 128 + k] : 0.f;
        Bs[m * 129 + k] = Wl[idx];            // m plays role of j here
        Bs[(128 + m) * 129 + k] = Wr[idx];
    }
    __syncthreads();

    const int tm = (tid & 15) * 8;   // 16 groups * 8 = 128 rows
    const int tj = (tid >> 4) * 8;   // 32 groups * 8 = 256 cols
    float acc[8][8];
#pragma unroll
    for (int i = 0; i < 8; i++)
#pragma unroll
        for (int j = 0; j < 8; j++) acc[i][j] = 0.f;

#pragma unroll 4
    for (int k = 0; k < 128; k++) {
        float a[8], b[8];
#pragma unroll
        for (int i = 0; i < 8; i++) a[i] = As[(tm + i) * 129 + k];
#pragma unroll
        for (int j = 0; j < 8; j++) b[j] = Bs[(tj + j) * 129 + k];
#pragma unroll
        for (int i = 0; i < 8; i++)
#pragma unroll
            for (int j = 0; j < 8; j++) acc[i][j] = fmaf(a[i], b[j], acc[i][j]);
    }

    const bool isP = (tj >= 128);
    float bj[8];
#pragma unroll
    for (int j = 0; j < 8; j++) bj[j] = isP ? bias[tj - 128 + j] : 0.f;

#pragma unroll
    for (int i = 0; i < 8; i++) {
        int gm = m0 + tm + i;
        if (gm >= n) continue;
        float4 v0 = make_float4(acc[i][0] + bj[0], acc[i][1] + bj[1],
                                acc[i][2] + bj[2], acc[i][3] + bj[3]);
        float4 v1 = make_float4(acc[i][4] + bj[4], acc[i][5] + bj[5],
                                acc[i][6] + bj[6], acc[i][7] + bj[7]);
        float* dst = isP ? (d_P1 + (size_t)gm * 128 + (tj - 128))
                         : (d_Z1 + (size_t)gm * 128 + tj);
        *(float4*)dst = v0;
        *(float4*)(dst + 4) = v1;
    }
}

// ---------------- agg1: h = P1 + mean-gather(Z1); BN partial sums ----------------
__global__ __launch_bounds__(256)
void k_agg1(int n) {
    __shared__ float ssum[128], ssq[128];
    int tid = threadIdx.x;
    if (tid < 128) { ssum[tid] = 0.f; ssq[tid] = 0.f; }
    __syncthreads();
    int lane = tid & 31, warp = tid >> 5;
    int node = blockIdx.x * 8 + warp;
    if (node < n) {
        int a = d_off[node], b = d_off[node + 1];
        float4 acc = make_float4(0.f, 0.f, 0.f, 0.f);
        int e = a;
        for (; e + 4 <= b; e += 4) {
            int s0 = d_srcs[e], s1 = d_srcs[e + 1], s2 = d_srcs[e + 2], s3 = d_srcs[e + 3];
            float4 v0 = *(const float4*)&d_Z1[(size_t)s0 * 128 + lane * 4];
            float4 v1 = *(const float4*)&d_Z1[(size_t)s1 * 128 + lane * 4];
            float4 v2 = *(const float4*)&d_Z1[(size_t)s2 * 128 + lane * 4];
            float4 v3 = *(const float4*)&d_Z1[(size_t)s3 * 128 + lane * 4];
            acc.x += (v0.x + v1.x) + (v2.x + v3.x);
            acc.y += (v0.y + v1.y) + (v2.y + v3.y);
            acc.z += (v0.z + v1.z) + (v2.z + v3.z);
            acc.w += (v0.w + v1.w) + (v2.w + v3.w);
        }
        for (; e < b; e++) {
            int s = d_srcs[e];
            float4 v = *(const float4*)&d_Z1[(size_t)s * 128 + lane * 4];
            acc.x += v.x; acc.y += v.y; acc.z += v.z; acc.w += v.w;
        }
        int cnt = b - a;
        float inv = 1.0f / (float)(cnt > 0 ? cnt : 1);
        float4 p = *(const float4*)&d_P1[(size_t)node * 128 + lane * 4];
        float4 h;
        h.x = fmaf(acc.x, inv, p.x);
        h.y = fmaf(acc.y, inv, p.y);
        h.z = fmaf(acc.z, inv, p.z);
        h.w = fmaf(acc.w, inv, p.w);
        *(float4*)&d_P1[(size_t)node * 128 + lane * 4] = h;
        int c = lane * 4;
        atomicAdd(&ssum[c + 0], h.x); atomicAdd(&ssq[c + 0], h.x * h.x);
        atomicAdd(&ssum[c + 1], h.y); atomicAdd(&ssq[c + 1], h.y * h.y);
        atomicAdd(&ssum[c + 2], h.z); atomicAdd(&ssq[c + 2], h.z * h.z);
        atomicAdd(&ssum[c + 3], h.w); atomicAdd(&ssq[c + 3], h.w * h.w);
    }
    __syncthreads();
    if (tid < 128) {
        atomicAdd(&d_bnsum[tid], (double)ssum[tid]);
        atomicAdd(&d_bnsq[tid], (double)ssq[tid]);
    }
}

// ---------------- BN finalize ----------------
__global__ void k_bnfin(const float* __restrict__ gamma, const float* __restrict__ beta, int n) {
    int c = threadIdx.x;  // 128 threads
    double mean = d_bnsum[c] / (double)n;
    double var = d_bnsq[c] / (double)n - mean * mean;
    float rs = rsqrtf((float)var + 1e-5f);
    float sc = gamma[c] * rs;
    d_scale[c] = sc;
    d_shift[c] = beta[c] - (float)mean * sc;
}

// ---------------- GEMM2: hn = relu(BN(h)); Z2 = hn@W2_l^T ; P2 = hn@W2_r^T ----------------
__global__ __launch_bounds__(512, 1)
void k_gemm2(const float* __restrict__ Wl, const float* __restrict__ Wr, int n) {
    extern __shared__ float sm[];
    float* As  = sm;                  // [128][129]
    float* Bs  = sm + 128 * 129;      // [128][129]
    float* ssc = Bs + 128 * 129;      // [128]
    float* ssh = ssc + 128;           // [128]
    const int tid = threadIdx.x;
    if (tid < 128) { ssc[tid] = d_scale[tid]; ssh[tid] = d_shift[tid]; }
    __syncthreads();
    const int m0 = blockIdx.x * 128;

    for (int idx = tid; idx < 128 * 128; idx += 512) {
        int m = idx >> 7, k = idx & 127;
        int gm = m0 + m;
        float v = 0.f;
        if (gm < n) {
            v = d_P1[(size_t)gm * 128 + k];
            v = fmaxf(fmaf(v, ssc[k], ssh[k]), 0.f);
        }
        As[m * 129 + k] = v;
    }
    for (int idx = tid; idx < 64 * 128; idx += 512) {
        int j = idx >> 7, k = idx & 127;
        Bs[j * 129 + k] = Wl[idx];
        Bs[(64 + j) * 129 + k] = Wr[idx];
    }
    __syncthreads();

    const int tm = (tid & 15) * 8;   // 128 rows
    const int tj = (tid >> 4) * 4;   // 32 groups * 4 = 128 cols
    float acc[8][4];
#pragma unroll
    for (int i = 0; i < 8; i++)
#pragma unroll
        for (int j = 0; j < 4; j++) acc[i][j] = 0.f;

#pragma unroll 4
    for (int k = 0; k < 128; k++) {
        float a[8], b[4];
#pragma unroll
        for (int i = 0; i < 8; i++) a[i] = As[(tm + i) * 129 + k];
#pragma unroll
        for (int j = 0; j < 4; j++) b[j] = Bs[(tj + j) * 129 + k];
#pragma unroll
        for (int i = 0; i < 8; i++)
#pragma unroll
            for (int j = 0; j < 4; j++) acc[i][j] = fmaf(a[i], b[j], acc[i][j]);
    }

    float* Z2 = d_Z1;
    float* P2 = d_Z1 + (size_t)n * 64;
    const bool isP = (tj >= 64);
#pragma unroll
    for (int i = 0; i < 8; i++) {
        int gm = m0 + tm + i;
        if (gm >= n) continue;
        float4 v = make_float4(acc[i][0], acc[i][1], acc[i][2], acc[i][3]);
        float* dst = isP ? (P2 + (size_t)gm * 64 + (tj - 64))
                         : (Z2 + (size_t)gm * 64 + tj);
        *(float4*)dst = v;
    }
}

// ---------------- agg2 + bias + log_softmax ----------------
__global__ __launch_bounds__(256)
void k_agg2(const float* __restrict__ b2, float* __restrict__ out, int n) {
    int tid = threadIdx.x, lane = tid & 31, warp = tid >> 5;
    int node = blockIdx.x * 8 + warp;
    if (node >= n) return;
    const float* Z2 = d_Z1;
    const float* P2 = d_Z1 + (size_t)n * 64;
    int a = d_off[node], b = d_off[node + 1];
    float2 acc = make_float2(0.f, 0.f);
    int e = a;
    for (; e + 4 <= b; e += 4) {
        int s0 = d_srcs[e], s1 = d_srcs[e + 1], s2 = d_srcs[e + 2], s3 = d_srcs[e + 3];
        float2 v0 = *(const float2*)&Z2[(size_t)s0 * 64 + lane * 2];
        float2 v1 = *(const float2*)&Z2[(size_t)s1 * 64 + lane * 2];
        float2 v2 = *(const float2*)&Z2[(size_t)s2 * 64 + lane * 2];
        float2 v3 = *(const float2*)&Z2[(size_t)s3 * 64 + lane * 2];
        acc.x += (v0.x + v1.x) + (v2.x + v3.x);
        acc.y += (v0.y + v1.y) + (v2.y + v3.y);
    }
    for (; e < b; e++) {
        int s = d_srcs[e];
        float2 v = *(const float2*)&Z2[(size_t)s * 64 + lane * 2];
        acc.x += v.x; acc.y += v.y;
    }
    int cnt = b - a;
    float inv = 1.0f / (float)(cnt > 0 ? cnt : 1);
    float2 p = *(const float2*)&P2[(size_t)node * 64 + lane * 2];
    float v0 = fmaf(acc.x, inv, p.x) + b2[lane * 2];
    float v1 = fmaf(acc.y, inv, p.y) + b2[lane * 2 + 1];

    float m = fmaxf(v0, v1);
#pragma unroll
    for (int d = 16; d > 0; d >>= 1) m = fmaxf(m, __shfl_xor_sync(0xffffffffu, m, d));
    float s = expf(v0 - m) + expf(v1 - m);
#pragma unroll
    for (int d = 16; d > 0; d >>= 1) s += __shfl_xor_sync(0xffffffffu, s, d);
    float ls = logf(s);
    float2 o = make_float2(v0 - m - ls, v1 - m - ls);
    *(float2*)&out[(size_t)node * 64 + lane * 2] = o;
}

// ---------------- launch ----------------
extern "C" void kernel_launch(void* const* d_in, const int* in_sizes, int n_in,
                              void* d_out, int out_size) {
    const float* x     = (const float*)d_in[0];
    const int*   ei    = (const int*)d_in[1];     // int32: JAX x64 disabled
    const float* W1l   = (const float*)d_in[2];
    const float* b1l   = (const float*)d_in[3];
    const float* W1r   = (const float*)d_in[4];
    const float* gamma = (const float*)d_in[5];
    const float* beta  = (const float*)d_in[6];
    const float* W2l   = (const float*)d_in[7];
    const float* b2l   = (const float*)d_in[8];
    const float* W2r   = (const float*)d_in[9];
    float* out = (float*)d_out;

    int N_ = in_sizes[0] / 128;
    int E_ = in_sizes[1] / 2;

    const int SMEM1 = (128 * 129 + 256 * 129) * 4;          // 198144
    const int SMEM2 = (128 * 129 + 128 * 129 + 256) * 4;    // 133120
    cudaFuncSetAttribute(k_gemm1, cudaFuncAttributeMaxDynamicSharedMemorySize, SMEM1);
    cudaFuncSetAttribute(k_gemm2, cudaFuncAttributeMaxDynamicSharedMemorySize, SMEM2);

    k_init<<<(N_ + 511) / 512, 512>>>(N_);
    k_hist<<<(E_ + 255) / 256, 256>>>(ei, E_, N_);
    int nb = (N_ + 1023) / 1024;
    k_scan1<<<nb, 1024>>>(N_);
    k_scan2<<<1, 128>>>(nb);
    k_scan3<<<nb, 1024>>>(N_, E_);
    k_scatter<<<(E_ + 255) / 256, 256>>>(ei, E_, N_);

    k_gemm1<<<(N_ + 127) / 128, 512, SMEM1>>>(x, W1l, W1r, b1l, N_);
    k_agg1<<<(N_ + 7) / 8, 256>>>(N_);
    k_bnfin<<<1, 128>>>(gamma, beta, N_);
    k_gemm2<<<(N_ + 127) / 128, 512, SMEM2>>>(W2l, W2r, N_);
    k_agg2<<<(N_ + 7) / 8, 256>>>(b2l, out, N_);
}

// round 16
// speedup vs baseline: 1.0005x; 1.0003x over previous
#include <cuda_runtime.h>
#include <math.h>

#define MAXN 100000
#define MAXE 1600000

// ---------------- static device scratch (no allocations allowed) ----------------
__device__ int    d_deg[MAXN];
__device__ int    d_off[MAXN + 1];
__device__ int    d_pos[MAXN];
__device__ int    d_srcs[MAXE];
__device__ int    d_bsums[128];
__device__ float  d_Z1[(size_t)MAXN * 128];   // x@W1_l^T  (later reused as Z2|P2)
__device__ float  d_P1[(size_t)MAXN * 128];   // x@W1_r^T + b1, becomes h in-place
__device__ double d_bnsum[128];
__device__ double d_bnsq[128];
__device__ float  d_scale[128];
__device__ float  d_shift[128];

// ---------------- init: zero counters ----------------
__global__ void k_init(int n) {
    int i = blockIdx.x * 512 + threadIdx.x;
    if (i < n) { d_deg[i] = 0; d_pos[i] = 0; }
    if (i < 128) { d_bnsum[i] = 0.0; d_bnsq[i] = 0.0; }
}

// ---------------- CSR build (edge_index is int32: JAX default x64=off) ----------
__global__ void k_hist(const int* __restrict__ ei, int E, int n) {
    int e = blockIdx.x * 256 + threadIdx.x;
    if (e >= E) return;
    int d = ei[E + e];
    if ((unsigned)d < (unsigned)n) atomicAdd(&d_deg[d], 1);
}

__global__ void k_scan1(int n) {
    int i = blockIdx.x * 1024 + threadIdx.x;
    int v = (i < n) ? d_deg[i] : 0;
    int lane = threadIdx.x & 31, wid = threadIdx.x >> 5;
    int x = v;
#pragma unroll
    for (int d = 1; d < 32; d <<= 1) {
        int y = __shfl_up_sync(0xffffffffu, x, d);
        if (lane >= d) x += y;
    }
    __shared__ int ws[32];
    if (lane == 31) ws[wid] = x;
    __syncthreads();
    if (wid == 0) {
        int s = ws[lane];
#pragma unroll
        for (int d = 1; d < 32; d <<= 1) {
            int y = __shfl_up_sync(0xffffffffu, s, d);
            if (lane >= d) s += y;
        }
        ws[lane] = s;
    }
    __syncthreads();
    int pref = (wid > 0) ? ws[wid - 1] : 0;
    int incl = pref + x;
    if (i < n) d_off[i] = incl - v;
    if (threadIdx.x == 1023) d_bsums[blockIdx.x] = incl;
}

__global__ void k_scan2(int nb) {   // nb <= 128
    int t = threadIdx.x;
    int v = (t < nb) ? d_bsums[t] : 0;
    int lane = t & 31, wid = t >> 5;
    int x = v;
#pragma unroll
    for (int d = 1; d < 32; d <<= 1) {
        int y = __shfl_up_sync(0xffffffffu, x, d);
        if (lane >= d) x += y;
    }
    __shared__ int ws[4];
    if (lane == 31) ws[wid] = x;
    __syncthreads();
    int pref = 0;
    for (int w = 0; w < wid; w++) pref += ws[w];
    int incl = pref + x;
    if (t < nb) d_bsums[t] = incl - v;
}

__global__ void k_scan3(int n, int E) {
    int i = blockIdx.x * 1024 + threadIdx.x;
    if (i < n) d_off[i] += d_bsums[blockIdx.x];
    if (blockIdx.x == 0 && threadIdx.x == 0) d_off[n] = E;
}

__global__ void k_scatter(const int* __restrict__ ei, int E, int n) {
    int e = blockIdx.x * 256 + threadIdx.x;
    if (e >= E) return;
    int s = ei[e];
    int d = ei[E + e];
    if ((unsigned)d >= (unsigned)n || (unsigned)s >= (unsigned)n) return;
    int idx = d_off[d] + atomicAdd(&d_pos[d], 1);
    d_srcs[idx] = s;
}

// ---------------- GEMM1: Z1 = x@W1_l^T ; P1 = x@W1_r^T + b1 ----------------
// B = concat(W1_l, W1_r) as [256 rows j][128 cols k], fully smem-resident.
__global__ __launch_bounds__(512, 1)
void k_gemm1(const float* __restrict__ x, const float* __restrict__ Wl,
             const float* __restrict__ Wr, const float* __restrict__ bias, int n) {
    extern __shared__ float sm[];
    float* As = sm;               // [128][129]
    float* Bs = sm + 128 * 129;   // [256][129]
    const int tid = threadIdx.x;
    const int m0 = blockIdx.x * 128;

    for (int idx = tid; idx < 128 * 128; idx += 512) {
        int m = idx >> 7, k = idx & 127;
        int gm = m0 + m;
        As[m * 129 + k] = (gm < n) ? x[(size_t)gm * 128 + k] : 0.f;
        Bs[m * 129 + k] = Wl[idx];            // m plays role of j here
        Bs[(128 + m) * 129 + k] = Wr[idx];
    }
    __syncthreads();

    const int tm = (tid & 15) * 8;   // 16 groups * 8 = 128 rows
    const int tj = (tid >> 4) * 8;   // 32 groups * 8 = 256 cols
    float acc[8][8];
#pragma unroll
    for (int i = 0; i < 8; i++)
#pragma unroll
        for (int j = 0; j < 8; j++) acc[i][j] = 0.f;

#pragma unroll 4
    for (int k = 0; k < 128; k++) {
        float a[8], b[8];
#pragma unroll
        for (int i = 0; i < 8; i++) a[i] = As[(tm + i) * 129 + k];
#pragma unroll
        for (int j = 0; j < 8; j++) b[j] = Bs[(tj + j) * 129 + k];
#pragma unroll
        for (int i = 0; i < 8; i++)
#pragma unroll
            for (int j = 0; j < 8; j++) acc[i][j] = fmaf(a[i], b[j], acc[i][j]);
    }

    const bool isP = (tj >= 128);
    float bj[8];
#pragma unroll
    for (int j = 0; j < 8; j++) bj[j] = isP ? bias[tj - 128 + j] : 0.f;

#pragma unroll
    for (int i = 0; i < 8; i++) {
        int gm = m0 + tm + i;
        if (gm >= n) continue;
        float4 v0 = make_float4(acc[i][0] + bj[0], acc[i][1] + bj[1],
                                acc[i][2] + bj[2], acc[i][3] + bj[3]);
        float4 v1 = make_float4(acc[i][4] + bj[4], acc[i][5] + bj[5],
                                acc[i][6] + bj[6], acc[i][7] + bj[7]);
        float* dst = isP ? (d_P1 + (size_t)gm * 128 + (tj - 128))
                         : (d_Z1 + (size_t)gm * 128 + tj);
        *(float4*)dst = v0;
        *(float4*)(dst + 4) = v1;
    }
}

// ---------------- agg1: h = P1 + mean-gather(Z1); BN partial sums ----------------
__global__ __launch_bounds__(256)
void k_agg1(int n) {
    __shared__ float ssum[128], ssq[128];
    int tid = threadIdx.x;
    if (tid < 128) { ssum[tid] = 0.f; ssq[tid] = 0.f; }
    __syncthreads();
    int lane = tid & 31, warp = tid >> 5;
    int node = blockIdx.x * 8 + warp;
    if (node < n) {
        int a = d_off[node], b = d_off[node + 1];
        float4 acc = make_float4(0.f, 0.f, 0.f, 0.f);
        int e = a;
        for (; e + 4 <= b; e += 4) {
            int s0 = d_srcs[e], s1 = d_srcs[e + 1], s2 = d_srcs[e + 2], s3 = d_srcs[e + 3];
            float4 v0 = *(const float4*)&d_Z1[(size_t)s0 * 128 + lane * 4];
            float4 v1 = *(const float4*)&d_Z1[(size_t)s1 * 128 + lane * 4];
            float4 v2 = *(const float4*)&d_Z1[(size_t)s2 * 128 + lane * 4];
            float4 v3 = *(const float4*)&d_Z1[(size_t)s3 * 128 + lane * 4];
            acc.x += (v0.x + v1.x) + (v2.x + v3.x);
            acc.y += (v0.y + v1.y) + (v2.y + v3.y);
            acc.z += (v0.z + v1.z) + (v2.z + v3.z);
            acc.w += (v0.w + v1.w) + (v2.w + v3.w);
        }
        for (; e < b; e++) {
            int s = d_srcs[e];
            float4 v = *(const float4*)&d_Z1[(size_t)s * 128 + lane * 4];
            acc.x += v.x; acc.y += v.y; acc.z += v.z; acc.w += v.w;
        }
        int cnt = b - a;
        float inv = 1.0f / (float)(cnt > 0 ? cnt : 1);
        float4 p = *(const float4*)&d_P1[(size_t)node * 128 + lane * 4];
        float4 h;
        h.x = fmaf(acc.x, inv, p.x);
        h.y = fmaf(acc.y, inv, p.y);
        h.z = fmaf(acc.z, inv, p.z);
        h.w = fmaf(acc.w, inv, p.w);
        *(float4*)&d_P1[(size_t)node * 128 + lane * 4] = h;
        int c = lane * 4;
        atomicAdd(&ssum[c + 0], h.x); atomicAdd(&ssq[c + 0], h.x * h.x);
        atomicAdd(&ssum[c + 1], h.y); atomicAdd(&ssq[c + 1], h.y * h.y);
        atomicAdd(&ssum[c + 2], h.z); atomicAdd(&ssq[c + 2], h.z * h.z);
        atomicAdd(&ssum[c + 3], h.w); atomicAdd(&ssq[c + 3], h.w * h.w);
    }
    __syncthreads();
    if (tid < 128) {
        atomicAdd(&d_bnsum[tid], (double)ssum[tid]);
        atomicAdd(&d_bnsq[tid], (double)ssq[tid]);
    }
}

// ---------------- BN finalize ----------------
__global__ void k_bnfin(const float* __restrict__ gamma, const float* __restrict__ beta, int n) {
    int c = threadIdx.x;  // 128 threads
    double mean = d_bnsum[c] / (double)n;
    double var = d_bnsq[c] / (double)n - mean * mean;
    float rs = rsqrtf((float)var + 1e-5f);
    float sc = gamma[c] * rs;
    d_scale[c] = sc;
    d_shift[c] = beta[c] - (float)mean * sc;
}

// ---------------- GEMM2: hn = relu(BN(h)); Z2 = hn@W2_l^T ; P2 = hn@W2_r^T ----------------
__global__ __launch_bounds__(512, 1)
void k_gemm2(const float* __restrict__ Wl, const float* __restrict__ Wr, int n) {
    extern __shared__ float sm[];
    float* As  = sm;                  // [128][129]
    float* Bs  = sm + 128 * 129;      // [128][129]
    float* ssc = Bs + 128 * 129;      // [128]
    float* ssh = ssc + 128;           // [128]
    const int tid = threadIdx.x;
    if (tid < 128) { ssc[tid] = d_scale[tid]; ssh[tid] = d_shift[tid]; }
    __syncthreads();
    const int m0 = blockIdx.x * 128;

    for (int idx = tid; idx < 128 * 128; idx += 512) {
        int m = idx >> 7, k = idx & 127;
        int gm = m0 + m;
        float v = 0.f;
        if (gm < n) {
            v = d_P1[(size_t)gm * 128 + k];
            v = fmaxf(fmaf(v, ssc[k], ssh[k]), 0.f);
        }
        As[m * 129 + k] = v;
    }
    for (int idx = tid; idx < 64 * 128; idx += 512) {
        int j = idx >> 7, k = idx & 127;
        Bs[j * 129 + k] = Wl[idx];
        Bs[(64 + j) * 129 + k] = Wr[idx];
    }
    __syncthreads();

    const int tm = (tid & 15) * 8;   // 128 rows
    const int tj = (tid >> 4) * 4;   // 32 groups * 4 = 128 cols
    float acc[8][4];
#pragma unroll
    for (int i = 0; i < 8; i++)
#pragma unroll
        for (int j = 0; j < 4; j++) acc[i][j] = 0.f;

#pragma unroll 4
    for (int k = 0; k < 128; k++) {
        float a[8], b[4];
#pragma unroll
        for (int i = 0; i < 8; i++) a[i] = As[(tm + i) * 129 + k];
#pragma unroll
        for (int j = 0; j < 4; j++) b[j] = Bs[(tj + j) * 129 + k];
#pragma unroll
        for (int i = 0; i < 8; i++)
#pragma unroll
            for (int j = 0; j < 4; j++) acc[i][j] = fmaf(a[i], b[j], acc[i][j]);
    }

    float* Z2 = d_Z1;
    float* P2 = d_Z1 + (size_t)n * 64;
    const bool isP = (tj >= 64);
#pragma unroll
    for (int i = 0; i < 8; i++) {
        int gm = m0 + tm + i;
        if (gm >= n) continue;
        float4 v = make_float4(acc[i][0], acc[i][1], acc[i][2], acc[i][3]);
        float* dst = isP ? (P2 + (size_t)gm * 64 + (tj - 64))
                         : (Z2 + (size_t)gm * 64 + tj);
        *(float4*)dst = v;
    }
}

// ---------------- agg2 + bias + log_softmax ----------------
__global__ __launch_bounds__(256)
void k_agg2(const float* __restrict__ b2, float* __restrict__ out, int n) {
    int tid = threadIdx.x, lane = tid & 31, warp = tid >> 5;
    int node = blockIdx.x * 8 + warp;
    if (node >= n) return;
    const float* Z2 = d_Z1;
    const float* P2 = d_Z1 + (size_t)n * 64;
    int a = d_off[node], b = d_off[node + 1];
    float2 acc = make_float2(0.f, 0.f);
    int e = a;
    for (; e + 4 <= b; e += 4) {
        int s0 = d_srcs[e], s1 = d_srcs[e + 1], s2 = d_srcs[e + 2], s3 = d_srcs[e + 3];
        float2 v0 = *(const float2*)&Z2[(size_t)s0 * 64 + lane * 2];
        float2 v1 = *(const float2*)&Z2[(size_t)s1 * 64 + lane * 2];
        float2 v2 = *(const float2*)&Z2[(size_t)s2 * 64 + lane * 2];
        float2 v3 = *(const float2*)&Z2[(size_t)s3 * 64 + lane * 2];
        acc.x += (v0.x + v1.x) + (v2.x + v3.x);
        acc.y += (v0.y + v1.y) + (v2.y + v3.y);
    }
    for (; e < b; e++) {
        int s = d_srcs[e];
        float2 v = *(const float2*)&Z2[(size_t)s * 64 + lane * 2];
        acc.x += v.x; acc.y += v.y;
    }
    int cnt = b - a;
    float inv = 1.0f / (float)(cnt > 0 ? cnt : 1);
    float2 p = *(const float2*)&P2[(size_t)node * 64 + lane * 2];
    float v0 = fmaf(acc.x, inv, p.x) + b2[lane * 2];
    float v1 = fmaf(acc.y, inv, p.y) + b2[lane * 2 + 1];

    float m = fmaxf(v0, v1);
#pragma unroll
    for (int d = 16; d > 0; d >>= 1) m = fmaxf(m, __shfl_xor_sync(0xffffffffu, m, d));
    float s = expf(v0 - m) + expf(v1 - m);
#pragma unroll
    for (int d = 16; d > 0; d >>= 1) s += __shfl_xor_sync(0xffffffffu, s, d);
    float ls = logf(s);
    float2 o = make_float2(v0 - m - ls, v1 - m - ls);
    *(float2*)&out[(size_t)node * 64 + lane * 2] = o;
}

// ---------------- launch ----------------
extern "C" void kernel_launch(void* const* d_in, const int* in_sizes, int n_in,
                              void* d_out, int out_size) {
    const float* x     = (const float*)d_in[0];
    const int*   ei    = (const int*)d_in[1];     // int32: JAX x64 disabled
    const float* W1l   = (const float*)d_in[2];
    const float* b1l   = (const float*)d_in[3];
    const float* W1r   = (const float*)d_in[4];
    const float* gamma = (const float*)d_in[5];
    const float* beta  = (const float*)d_in[6];
    const float* W2l   = (const float*)d_in[7];
    const float* b2l   = (const float*)d_in[8];
    const float* W2r   = (const float*)d_in[9];
    float* out = (float*)d_out;

    int N_ = in_sizes[0] / 128;
    int E_ = in_sizes[1] / 2;

    const int SMEM1 = (128 * 129 + 256 * 129) * 4;          // 198144
    const int SMEM2 = (128 * 129 + 128 * 129 + 256) * 4;    // 133120
    cudaFuncSetAttribute(k_gemm1, cudaFuncAttributeMaxDynamicSharedMemorySize, SMEM1);
    cudaFuncSetAttribute(k_gemm2, cudaFuncAttributeMaxDynamicSharedMemorySize, SMEM2);

    k_init<<<(N_ + 511) / 512, 512>>>(N_);
    k_hist<<<(E_ + 255) / 256, 256>>>(ei, E_, N_);
    int nb = (N_ + 1023) / 1024;
    k_scan1<<<nb, 1024>>>(N_);
    k_scan2<<<1, 128>>>(nb);
    k_scan3<<<nb, 1024>>>(N_, E_);
    k_scatter<<<(E_ + 255) / 256, 256>>>(ei, E_, N_);

    k_gemm1<<<(N_ + 127) / 128, 512, SMEM1>>>(x, W1l, W1r, b1l, N_);
    k_agg1<<<(N_ + 7) / 8, 256>>>(N_);
    k_bnfin<<<1, 128>>>(gamma, beta, N_);
    k_gemm2<<<(N_ + 127) / 128, 512, SMEM2>>>(W2l, W2r, N_);
    k_agg2<<<(N_ + 7) / 8, 256>>>(b2l, out, N_);
}